// round 14
// baseline (speedup 1.0000x reference)
#include <cuda_runtime.h>
#include <cstdint>
#include <cstddef>

#define BB 128
#define LL 1024
#define TT 64
#define DD 256
#define VV 30000
#define MEET 511   // forward covers t=0..511 (511 matvec steps), backward t=1023..512 (512 steps)

#define LN2f 0.6931471805599453f

// Vocab-level emission tables (L2-resident: 7.68 MB each)
__device__ float gEW[VV * TT];    // embed@W + b
__device__ float gExp[VV * TT];   // exp(embed@W + b)

typedef unsigned long long u64;

// ---------------- packed f32x2 helpers ----------------
__device__ __forceinline__ u64 fma2(u64 a, u64 b, u64 c) {
    u64 d;
    asm("fma.rn.f32x2 %0, %1, %2, %3;" : "=l"(d) : "l"(a), "l"(b), "l"(c));
    return d;
}
__device__ __forceinline__ u64 add2(u64 a, u64 b) {
    u64 d;
    asm("add.rn.f32x2 %0, %1, %2;" : "=l"(d) : "l"(a), "l"(b));
    return d;
}
__device__ __forceinline__ u64 mul2(u64 a, u64 b) {
    u64 d;
    asm("mul.rn.f32x2 %0, %1, %2;" : "=l"(d) : "l"(a), "l"(b));
    return d;
}
__device__ __forceinline__ u64 pack2(float lo, float hi) {
    u64 d;
    asm("mov.b64 %0, {%1, %2};" : "=l"(d) : "f"(lo), "f"(hi));
    return d;
}
__device__ __forceinline__ float2 unpack2(u64 v) {
    float lo, hi;
    asm("mov.b64 {%0, %1}, %2;" : "=f"(lo), "=f"(hi) : "l"(v));
    return make_float2(lo, hi);
}
__device__ __forceinline__ float frcp(float x) {
    float r;
    asm("rcp.approx.f32 %0, %1;" : "=r"(*(unsigned*)&r) : "r"(*(unsigned*)&x));
    return r;
}
__device__ __forceinline__ void named_bar(int id, int cnt) {
    asm volatile("bar.sync %0, %1;" :: "r"(id), "r"(cnt) : "memory");
}

// ---------------- Kernel A: EW = embed @ W + b over the VOCAB ----------------
#define ESTRIDE 68
#define SMEM_A_BYTES ((16384 + 128 * ESTRIDE) * 4)

__global__ void __launch_bounds__(256, 2)
emis_kernel(const float* __restrict__ embed, const float* __restrict__ W,
            const float* __restrict__ bias, float* __restrict__ out_scalar) {
    extern __shared__ float sm[];
    float* w_sh = sm;             // [256][64]
    float* e_sh = sm + 16384;     // [128][ESTRIDE]

    const int tid = threadIdx.x;
    if (blockIdx.x == 0 && tid == 0) *out_scalar = 0.0f;

    const int row_base = blockIdx.x * 128;

    {
        const float4* src = (const float4*)W;
        float4* dst = (float4*)w_sh;
        #pragma unroll
        for (int i = 0; i < 16; i++) dst[tid + 256 * i] = src[tid + 256 * i];
    }
    __syncthreads();

    const int lg = tid & 7;
    const int tg = tid >> 3;
    const int warp = tid >> 5, lane = tid & 31;

    u64 acc[4][4];
    #pragma unroll
    for (int t = 0; t < 4; t++)
        #pragma unroll
        for (int q = 0; q < 4; q++) acc[t][q] = 0ull;

    for (int c = 0; c < 4; c++) {
        const int c0 = c * 64;
        #pragma unroll
        for (int pr = warp; pr < 64; pr += 8) {
            int tl = pr * 2 + (lane >> 4);
            int r = row_base + tl; if (r > VV - 1) r = VV - 1;
            int d4 = lane & 15;
            float4 v = *(const float4*)(embed + (size_t)r * DD + c0 + d4 * 4);
            *(float4*)&e_sh[tl * ESTRIDE + d4 * 4] = v;
        }
        __syncthreads();

        #pragma unroll 8
        for (int d = 0; d < 64; d++) {
            const ulonglong2* wrow = (const ulonglong2*)&w_sh[(c0 + d) * 64 + (lg << 3)];
            ulonglong2 w01 = wrow[0];
            ulonglong2 w23 = wrow[1];
            #pragma unroll
            for (int t = 0; t < 4; t++) {
                float e = e_sh[(tg * 4 + t) * ESTRIDE + d];
                u64 e2 = pack2(e, e);
                acc[t][0] = fma2(e2, w01.x, acc[t][0]);
                acc[t][1] = fma2(e2, w01.y, acc[t][1]);
                acc[t][2] = fma2(e2, w23.x, acc[t][2]);
                acc[t][3] = fma2(e2, w23.y, acc[t][3]);
            }
        }
        __syncthreads();
    }

    float bb[8];
    #pragma unroll
    for (int k = 0; k < 8; k++) bb[k] = bias[(lg << 3) + k];

    #pragma unroll
    for (int t = 0; t < 4; t++) {
        int r = row_base + tg * 4 + t;
        if (r < VV) {
            float2 p0 = unpack2(acc[t][0]);
            float2 p1 = unpack2(acc[t][1]);
            float2 p2 = unpack2(acc[t][2]);
            float2 p3 = unpack2(acc[t][3]);
            float v[8] = { p0.x + bb[0], p0.y + bb[1], p1.x + bb[2], p1.y + bb[3],
                           p2.x + bb[4], p2.y + bb[5], p3.x + bb[6], p3.y + bb[7] };
            float4* ow = (float4*)(gEW + (size_t)r * TT + (lg << 3));
            ow[0] = make_float4(v[0], v[1], v[2], v[3]);
            ow[1] = make_float4(v[4], v[5], v[6], v[7]);
            float4* oe = (float4*)(gExp + (size_t)r * TT + (lg << 3));
            oe[0] = make_float4(__expf(v[0]), __expf(v[1]), __expf(v[2]), __expf(v[3]));
            oe[1] = make_float4(__expf(v[4]), __expf(v[5]), __expf(v[6]), __expf(v[7]));
        }
    }
}

// ---------------- Kernel B: CRF NLL, bidirectional single-warp scans ----------------
// 128 CTAs x 256 threads.
//   warp 0: forward scan, 2 labels/lane, intra-warp exchange (no bar.sync)
//   warp 1: backward scan, 2 sources/lane, intra-warp exchange
//   warps 2-7: gold-score partials in prologue, then exit
// Normalization every 4th step only (scale tracked via log2(S)).
__global__ void __launch_bounds__(256)
crf_kernel(const int* __restrict__ x, const int* __restrict__ tags,
           const float* __restrict__ trans, float* __restrict__ out) {
    __shared__ float trans_sh[64 * 64];
    __shared__ __align__(16) float shF[2][64];
    __shared__ __align__(16) float shG[2][64];
    __shared__ float sF[64], sG[64];
    __shared__ float sgold[8];
    __shared__ float Cshare[2];
    __shared__ int sx[LL], stag[LL];

    const int tid = threadIdx.x;
    const int wid = tid >> 5, lane = tid & 31;
    const int b = blockIdx.x;
    const int base = b * LL;

    #pragma unroll
    for (int i = tid; i < 4096; i += 256) trans_sh[i] = trans[i];
    #pragma unroll
    for (int k = 0; k < 4; k++) {
        sx[tid + 256 * k]   = x[base + tid + 256 * k];
        stag[tid + 256 * k] = tags[base + tid + 256 * k];
    }
    __syncthreads();

    // Gold-path partials over all 256 threads (random L2 lookups, high MLP)
    {
        float gp = 0.0f;
        #pragma unroll
        for (int t = tid; t < LL; t += 256)
            gp += gEW[(size_t)sx[t] * TT + stag[t]];
        #pragma unroll
        for (int t = tid; t < LL - 1; t += 256)
            gp += trans_sh[stag[t] * 64 + stag[t + 1]];
        #pragma unroll
        for (int off = 16; off; off >>= 1)
            gp += __shfl_xor_sync(0xffffffffu, gp, off);
        if (lane == 0) sgold[wid] = gp;
    }
    __syncthreads();

    if (wid >= 2) return;   // helper warps done (sgold visible after the barrier)

    const int j0 = 2 * lane, j1 = 2 * lane + 1;

    if (wid == 0) {
        // ===================== FORWARD (warp 0, one SMSP) =====================
        // E columns j0, j1 in registers, packed by source-pairs
        u64 EF0[32], EF1[32];
        #pragma unroll
        for (int k = 0; k < 32; k++) {
            EF0[k] = pack2(__expf(trans_sh[(2 * k) * 64 + j0]),
                           __expf(trans_sh[(2 * k + 1) * 64 + j0]));
            EF1[k] = pack2(__expf(trans_sh[(2 * k) * 64 + j1]),
                           __expf(trans_sh[(2 * k + 1) * 64 + j1]));
        }
        const u64 Est = pack2(__expf(trans_sh[j0]), __expf(trans_sh[j1]));

        // t = 0
        float2 e0 = *(const float2*)(gExp + (size_t)sx[0] * TT + j0);
        u64 p = mul2(pack2(e0.x, e0.y), Est);
        float Cf = 0.0f;

        u64 embuf[4];
        #pragma unroll
        for (int k = 1; k <= 4; k++) {
            float2 e = *(const float2*)(gExp + (size_t)sx[k] * TT + j0);
            embuf[k & 3] = pack2(e.x, e.y);
        }

        #pragma unroll 4
        for (int t = 1; t <= MEET; t++) {
            u64 em = embuf[t & 3];
            if (t + 4 <= MEET) {
                float2 e = *(const float2*)(gExp + (size_t)sx[t + 4] * TT + j0);
                embuf[t & 3] = pack2(e.x, e.y);
            }

            *(u64*)&shF[t & 1][j0] = p;       // STS.64, natural pair layout
            __syncwarp();

            const ulonglong2* sp = (const ulonglong2*)shF[t & 1];
            u64 A0 = 0ull, B0 = 0ull, A1 = 0ull, B1 = 0ull;
            if ((t & 3) == 0) {
                u64 sacc = 0ull;
                #pragma unroll
                for (int q = 0; q < 16; q++) {
                    ulonglong2 u = sp[q];     // pairs (p_{4q},p_{4q+1}), (p_{4q+2},p_{4q+3})
                    A0 = fma2(u.x, EF0[2 * q], A0); B0 = fma2(u.y, EF0[2 * q + 1], B0);
                    A1 = fma2(u.x, EF1[2 * q], A1); B1 = fma2(u.y, EF1[2 * q + 1], B1);
                    if (q == 4) sacc = add2(u.x, u.y);                 // labels 16..19
                    if (q == 5) sacc = add2(sacc, add2(u.x, u.y));     // labels 20..23
                }
                float2 Sf = unpack2(sacc);
                float S = Sf.x + Sf.y;        // subset sum (8 healthy labels) > 0
                float2 f0 = unpack2(add2(A0, B0));
                float2 f1 = unpack2(add2(A1, B1));
                float invS = frcp(S);
                Cf += __log2f(S);
                p = mul2(mul2(pack2(f0.x + f0.y, f1.x + f1.y), em), pack2(invS, invS));
            } else {
                #pragma unroll
                for (int q = 0; q < 16; q++) {
                    ulonglong2 u = sp[q];
                    A0 = fma2(u.x, EF0[2 * q], A0); B0 = fma2(u.y, EF0[2 * q + 1], B0);
                    A1 = fma2(u.x, EF1[2 * q], A1); B1 = fma2(u.y, EF1[2 * q + 1], B1);
                }
                float2 f0 = unpack2(add2(A0, B0));
                float2 f1 = unpack2(add2(A1, B1));
                p = mul2(pack2(f0.x + f0.y, f1.x + f1.y), em);  // carry scale; bounded <=4 steps
            }
        }
        *(u64*)&sF[j0] = p;                   // f_MEET pair, scale 2^Cf
        if (lane == 0) Cshare[0] = Cf;
    } else {
        // ===================== BACKWARD (warp 1, another SMSP) =====================
        // E rows i0=j0, i1=j1 in registers, packed by dest-pairs
        u64 EB0[32], EB1[32];
        #pragma unroll
        for (int k = 0; k < 32; k++) {
            EB0[k] = pack2(__expf(trans_sh[j0 * 64 + 2 * k]),
                           __expf(trans_sh[j0 * 64 + 2 * k + 1]));
            EB1[k] = pack2(__expf(trans_sh[j1 * 64 + 2 * k]),
                           __expf(trans_sh[j1 * 64 + 2 * k + 1]));
        }

        u64 g = pack2(__expf(trans_sh[j0 * 64 + 1]), __expf(trans_sh[j1 * 64 + 1]));  // Eend
        float Cb = 0.0f;

        u64 embuf[4];
        #pragma unroll
        for (int k = 0; k < 4; k++) {
            float2 e = *(const float2*)(gExp + (size_t)sx[LL - 1 - k] * TT + j0);
            embuf[(LL - 1 - k) & 3] = pack2(e.x, e.y);
        }

        #pragma unroll 4
        for (int t = LL - 1; t > MEET; t--) {
            u64 pe = embuf[t & 3];
            if (t - 4 > MEET) {
                float2 e = *(const float2*)(gExp + (size_t)sx[t - 4] * TT + j0);
                embuf[t & 3] = pack2(e.x, e.y);
            }

            *(u64*)&shG[t & 1][j0] = mul2(pe, g);   // h_t pair
            __syncwarp();

            const ulonglong2* sp = (const ulonglong2*)shG[t & 1];
            u64 A0 = 0ull, B0 = 0ull, A1 = 0ull, B1 = 0ull;
            if ((t & 3) == 0) {
                u64 sacc = 0ull;
                #pragma unroll
                for (int q = 0; q < 16; q++) {
                    ulonglong2 u = sp[q];
                    A0 = fma2(u.x, EB0[2 * q], A0); B0 = fma2(u.y, EB0[2 * q + 1], B0);
                    A1 = fma2(u.x, EB1[2 * q], A1); B1 = fma2(u.y, EB1[2 * q + 1], B1);
                    if (q == 4) sacc = add2(u.x, u.y);
                    if (q == 5) sacc = add2(sacc, add2(u.x, u.y));
                }
                float2 Sf = unpack2(sacc);
                float S = Sf.x + Sf.y;
                float2 f0 = unpack2(add2(A0, B0));
                float2 f1 = unpack2(add2(A1, B1));
                float invS = frcp(S);
                Cb += __log2f(S);
                g = mul2(pack2(f0.x + f0.y, f1.x + f1.y), pack2(invS, invS));
            } else {
                #pragma unroll
                for (int q = 0; q < 16; q++) {
                    ulonglong2 u = sp[q];
                    A0 = fma2(u.x, EB0[2 * q], A0); B0 = fma2(u.y, EB0[2 * q + 1], B0);
                    A1 = fma2(u.x, EB1[2 * q], A1); B1 = fma2(u.y, EB1[2 * q + 1], B1);
                }
                float2 f0 = unpack2(add2(A0, B0));
                float2 f1 = unpack2(add2(A1, B1));
                g = pack2(f0.x + f0.y, f1.x + f1.y);   // carry scale
            }
        }
        *(u64*)&sG[j0] = g;                   // g_MEET pair, scale 2^Cb
        if (lane == 0) Cshare[1] = Cb;
    }

    named_bar(3, 64);   // warps 0-1 only (helpers have exited)

    if (tid == 0) {
        float Z = 0.0f, gold = 0.0f;
        #pragma unroll 8
        for (int k = 0; k < 64; k++) Z += sF[k] * sG[k];
        #pragma unroll
        for (int k = 0; k < 8; k++) gold += sgold[k];
        float logz = LN2f * (Cshare[0] + Cshare[1] + __log2f(Z));
        float score = gold + trans_sh[stag[0]] + trans_sh[stag[LL - 1] * 64 + 1];
        atomicAdd(out, logz - score);   // out = -sum(scores - log_z)
    }
}

// ---------------- launch ----------------
extern "C" void kernel_launch(void* const* d_in, const int* in_sizes, int n_in,
                              void* d_out, int out_size) {
    const int*   x     = (const int*)d_in[0];
    const int*   tags  = (const int*)d_in[1];
    // d_in[2] = mask (ignored by reference CRF)
    const float* embed = (const float*)d_in[3];
    const float* W     = (const float*)d_in[4];
    const float* bias  = (const float*)d_in[5];
    const float* trans = (const float*)d_in[6];
    float* out = (float*)d_out;

    static bool attr_set = false;
    if (!attr_set) {
        cudaFuncSetAttribute(emis_kernel, cudaFuncAttributeMaxDynamicSharedMemorySize, SMEM_A_BYTES);
        attr_set = true;
    }

    emis_kernel<<<(VV + 127) / 128, 256, SMEM_A_BYTES>>>(embed, W, bias, out);
    crf_kernel<<<BB, 256>>>(x, tags, trans, out);
}

// round 17
// speedup vs baseline: 1.9466x; 1.9466x over previous
#include <cuda_runtime.h>
#include <cstdint>
#include <cstddef>

#define BB 128
#define LL 1024
#define TT 64
#define DD 256
#define VV 30000
#define MEET 511   // forward covers t=0..511 (511 matvec steps), backward t=1023..512 (512 steps)

#define LN2f 0.6931471805599453f

// Vocab-level emission tables (L2-resident: 7.68 MB each)
__device__ float gEW[VV * TT];    // embed@W + b
__device__ float gExp[VV * TT];   // exp(embed@W + b)

typedef unsigned long long u64;

// ---------------- packed f32x2 helpers ----------------
__device__ __forceinline__ u64 fma2(u64 a, u64 b, u64 c) {
    u64 d;
    asm("fma.rn.f32x2 %0, %1, %2, %3;" : "=l"(d) : "l"(a), "l"(b), "l"(c));
    return d;
}
__device__ __forceinline__ u64 add2(u64 a, u64 b) {
    u64 d;
    asm("add.rn.f32x2 %0, %1, %2;" : "=l"(d) : "l"(a), "l"(b));
    return d;
}
__device__ __forceinline__ u64 pack2(float lo, float hi) {
    u64 d;
    asm("mov.b64 %0, {%1, %2};" : "=l"(d) : "f"(lo), "f"(hi));
    return d;
}
__device__ __forceinline__ float2 unpack2(u64 v) {
    float lo, hi;
    asm("mov.b64 {%0, %1}, %2;" : "=f"(lo), "=f"(hi) : "l"(v));
    return make_float2(lo, hi);
}
__device__ __forceinline__ float frcp(float x) {
    float r;
    asm("rcp.approx.f32 %0, %1;" : "=r"(*(unsigned*)&r) : "r"(*(unsigned*)&x));
    return r;
}
__device__ __forceinline__ void named_bar(int id, int cnt) {
    asm volatile("bar.sync %0, %1;" :: "r"(id), "r"(cnt) : "memory");
}

// ---------------- Kernel A: EW = embed @ W + b over the VOCAB ----------------
#define ESTRIDE 68
#define SMEM_A_BYTES ((16384 + 128 * ESTRIDE) * 4)

__global__ void __launch_bounds__(256, 2)
emis_kernel(const float* __restrict__ embed, const float* __restrict__ W,
            const float* __restrict__ bias, float* __restrict__ out_scalar) {
    extern __shared__ float sm[];
    float* w_sh = sm;             // [256][64]
    float* e_sh = sm + 16384;     // [128][ESTRIDE]

    const int tid = threadIdx.x;
    if (blockIdx.x == 0 && tid == 0) *out_scalar = 0.0f;

    const int row_base = blockIdx.x * 128;

    {
        const float4* src = (const float4*)W;
        float4* dst = (float4*)w_sh;
        #pragma unroll
        for (int i = 0; i < 16; i++) dst[tid + 256 * i] = src[tid + 256 * i];
    }
    __syncthreads();

    const int lg = tid & 7;
    const int tg = tid >> 3;
    const int warp = tid >> 5, lane = tid & 31;

    u64 acc[4][4];
    #pragma unroll
    for (int t = 0; t < 4; t++)
        #pragma unroll
        for (int q = 0; q < 4; q++) acc[t][q] = 0ull;

    for (int c = 0; c < 4; c++) {
        const int c0 = c * 64;
        #pragma unroll
        for (int pr = warp; pr < 64; pr += 8) {
            int tl = pr * 2 + (lane >> 4);
            int r = row_base + tl; if (r > VV - 1) r = VV - 1;
            int d4 = lane & 15;
            float4 v = *(const float4*)(embed + (size_t)r * DD + c0 + d4 * 4);
            *(float4*)&e_sh[tl * ESTRIDE + d4 * 4] = v;
        }
        __syncthreads();

        #pragma unroll 8
        for (int d = 0; d < 64; d++) {
            const ulonglong2* wrow = (const ulonglong2*)&w_sh[(c0 + d) * 64 + (lg << 3)];
            ulonglong2 w01 = wrow[0];
            ulonglong2 w23 = wrow[1];
            #pragma unroll
            for (int t = 0; t < 4; t++) {
                float e = e_sh[(tg * 4 + t) * ESTRIDE + d];
                u64 e2 = pack2(e, e);
                acc[t][0] = fma2(e2, w01.x, acc[t][0]);
                acc[t][1] = fma2(e2, w01.y, acc[t][1]);
                acc[t][2] = fma2(e2, w23.x, acc[t][2]);
                acc[t][3] = fma2(e2, w23.y, acc[t][3]);
            }
        }
        __syncthreads();
    }

    float bb[8];
    #pragma unroll
    for (int k = 0; k < 8; k++) bb[k] = bias[(lg << 3) + k];

    #pragma unroll
    for (int t = 0; t < 4; t++) {
        int r = row_base + tg * 4 + t;
        if (r < VV) {
            float2 p0 = unpack2(acc[t][0]);
            float2 p1 = unpack2(acc[t][1]);
            float2 p2 = unpack2(acc[t][2]);
            float2 p3 = unpack2(acc[t][3]);
            float v[8] = { p0.x + bb[0], p0.y + bb[1], p1.x + bb[2], p1.y + bb[3],
                           p2.x + bb[4], p2.y + bb[5], p3.x + bb[6], p3.y + bb[7] };
            float4* ow = (float4*)(gEW + (size_t)r * TT + (lg << 3));
            ow[0] = make_float4(v[0], v[1], v[2], v[3]);
            ow[1] = make_float4(v[4], v[5], v[6], v[7]);
            float4* oe = (float4*)(gExp + (size_t)r * TT + (lg << 3));
            oe[0] = make_float4(__expf(v[0]), __expf(v[1]), __expf(v[2]), __expf(v[3]));
            oe[1] = make_float4(__expf(v[4]), __expf(v[5]), __expf(v[6]), __expf(v[7]));
        }
    }
}

// ---------------- Kernel B: CRF NLL, bidirectional linear-domain scan ----------------
// 128 CTAs x 128 threads (R12 skeleton: fwd = warps 0-1, bwd = warps 2-3, disjoint SMSPs).
// Per-step: p' = (E^T p) * expem, normalized every 4th step (C2 += log2 S).
// 8 independent accumulators to halve the fma dependency chain.
__global__ void __launch_bounds__(128)
crf_kernel(const int* __restrict__ x, const int* __restrict__ tags,
           const float* __restrict__ trans, float* __restrict__ out) {
    __shared__ float trans_sh[64 * 64];
    __shared__ __align__(16) float shpF[2][64];
    __shared__ __align__(16) float shpG[2][64];
    __shared__ float sF[64], sG[64];
    __shared__ float redG[128];
    __shared__ float Cshare[2];
    __shared__ int sx[LL], stag[LL];

    const int tid = threadIdx.x;
    const int b = blockIdx.x;
    const int base = b * LL;

    #pragma unroll
    for (int i = tid; i < 4096; i += 128) trans_sh[i] = trans[i];
    #pragma unroll
    for (int k = 0; k < 8; k++) {
        sx[tid + 128 * k]   = x[base + tid + 128 * k];
        stag[tid + 128 * k] = tags[base + tid + 128 * k];
    }
    __syncthreads();

    // Gold-path partials, strided over all 128 threads (random L2 lookups, high MLP)
    float egold = 0.0f, tgold = 0.0f;
    #pragma unroll 4
    for (int t = tid; t < LL; t += 128)
        egold += gEW[(size_t)sx[t] * TT + stag[t]];
    #pragma unroll 4
    for (int t = tid; t < LL - 1; t += 128)
        tgold += trans_sh[stag[t] * 64 + stag[t + 1]];

    if (tid < 64) {
        // ===================== FORWARD (warps 0-1, SMSP 0/1) =====================
        const int j = tid;
        u64 E2[32];   // E column j, source-pairs
        #pragma unroll
        for (int i = 0; i < 32; i++)
            E2[i] = pack2(__expf(trans_sh[(2 * i) * 64 + j]),
                          __expf(trans_sh[(2 * i + 1) * 64 + j]));
        const float Estart = __expf(trans_sh[j]);

        float p = gExp[(size_t)sx[0] * TT + j] * Estart;
        float Cf = 0.0f;

        float embuf[4];
        #pragma unroll
        for (int k = 1; k <= 4; k++) embuf[k & 3] = gExp[(size_t)sx[k] * TT + j];

        #pragma unroll 4
        for (int t = 1; t <= MEET; t++) {
            float expem = embuf[t & 3];
            if (t + 4 <= MEET) embuf[t & 3] = gExp[(size_t)sx[t + 4] * TT + j];

            shpF[t & 1][j] = p;
            named_bar(1, 64);

            const ulonglong2* sp = (const ulonglong2*)shpF[t & 1];
            u64 ac[8];
            #pragma unroll
            for (int q = 0; q < 8; q++) ac[q] = 0ull;

            if ((t & 3) == 0) {
                u64 sacc = 0ull;
                #pragma unroll
                for (int q = 0; q < 16; q++) {
                    ulonglong2 u = sp[q];
                    ac[(2 * q) & 7]     = fma2(u.x, E2[2 * q],     ac[(2 * q) & 7]);
                    ac[(2 * q + 1) & 7] = fma2(u.y, E2[2 * q + 1], ac[(2 * q + 1) & 7]);
                    if (q == 4) sacc = add2(u.x, u.y);                 // labels 16..19
                    if (q == 5) sacc = add2(sacc, add2(u.x, u.y));     // labels 20..23
                }
                float2 Sf = unpack2(sacc);
                float S = Sf.x + Sf.y;            // subset sum (8 healthy labels) > 0
                u64 r = add2(add2(add2(ac[0], ac[1]), add2(ac[2], ac[3])),
                             add2(add2(ac[4], ac[5]), add2(ac[6], ac[7])));
                float2 sf = unpack2(r);
                float s = sf.x + sf.y;
                float invS = frcp(S);
                Cf += __log2f(S);
                p = s * expem * invS;
            } else {
                #pragma unroll
                for (int q = 0; q < 16; q++) {
                    ulonglong2 u = sp[q];
                    ac[(2 * q) & 7]     = fma2(u.x, E2[2 * q],     ac[(2 * q) & 7]);
                    ac[(2 * q + 1) & 7] = fma2(u.y, E2[2 * q + 1], ac[(2 * q + 1) & 7]);
                }
                u64 r = add2(add2(add2(ac[0], ac[1]), add2(ac[2], ac[3])),
                             add2(add2(ac[4], ac[5]), add2(ac[6], ac[7])));
                float2 sf = unpack2(r);
                p = (sf.x + sf.y) * expem;        // carry scale; bounded over <=4 steps
            }
        }
        sF[j] = p;                 // f_MEET, scale 2^Cf
        if (j == 0) Cshare[0] = Cf;
    } else {
        // ===================== BACKWARD (warps 2-3, SMSP 2/3) =====================
        const int i = tid - 64;
        u64 E2r[32];  // E row i, dest-pairs
        #pragma unroll
        for (int k = 0; k < 32; k++)
            E2r[k] = pack2(__expf(trans_sh[i * 64 + 2 * k]),
                           __expf(trans_sh[i * 64 + 2 * k + 1]));

        float g = __expf(trans_sh[i * 64 + 1]);   // Eend(i)
        float Cb = 0.0f;

        float embuf[4];
        #pragma unroll
        for (int k = 0; k < 4; k++) embuf[(LL - 1 - k) & 3] = gExp[(size_t)sx[LL - 1 - k] * TT + i];

        #pragma unroll 4
        for (int t = LL - 1; t > MEET; t--) {
            float pe = embuf[t & 3];
            if (t - 4 > MEET) embuf[t & 3] = gExp[(size_t)sx[t - 4] * TT + i];

            shpG[t & 1][i] = pe * g;              // h_t(i)
            named_bar(2, 64);

            const ulonglong2* sp = (const ulonglong2*)shpG[t & 1];
            u64 ac[8];
            #pragma unroll
            for (int q = 0; q < 8; q++) ac[q] = 0ull;

            if ((t & 3) == 0) {
                u64 sacc = 0ull;
                #pragma unroll
                for (int q = 0; q < 16; q++) {
                    ulonglong2 u = sp[q];
                    ac[(2 * q) & 7]     = fma2(u.x, E2r[2 * q],     ac[(2 * q) & 7]);
                    ac[(2 * q + 1) & 7] = fma2(u.y, E2r[2 * q + 1], ac[(2 * q + 1) & 7]);
                    if (q == 4) sacc = add2(u.x, u.y);
                    if (q == 5) sacc = add2(sacc, add2(u.x, u.y));
                }
                float2 Sf = unpack2(sacc);
                float S = Sf.x + Sf.y;
                u64 r = add2(add2(add2(ac[0], ac[1]), add2(ac[2], ac[3])),
                             add2(add2(ac[4], ac[5]), add2(ac[6], ac[7])));
                float2 sf = unpack2(r);
                float s = sf.x + sf.y;
                float invS = frcp(S);
                Cb += __log2f(S);
                g = s * invS;
            } else {
                #pragma unroll
                for (int q = 0; q < 16; q++) {
                    ulonglong2 u = sp[q];
                    ac[(2 * q) & 7]     = fma2(u.x, E2r[2 * q],     ac[(2 * q) & 7]);
                    ac[(2 * q + 1) & 7] = fma2(u.y, E2r[2 * q + 1], ac[(2 * q + 1) & 7]);
                }
                u64 r = add2(add2(add2(ac[0], ac[1]), add2(ac[2], ac[3])),
                             add2(add2(ac[4], ac[5]), add2(ac[6], ac[7])));
                float2 sf = unpack2(r);
                g = sf.x + sf.y;                  // carry scale
            }
        }
        sG[i] = g;                 // g_MEET, scale 2^Cb
        if (i == 0) Cshare[1] = Cb;
    }

    redG[tid] = egold + tgold;
    __syncthreads();

    if (tid == 0) {
        float Z = 0.0f, gold = 0.0f;
        #pragma unroll 8
        for (int k = 0; k < 64; k++) Z += sF[k] * sG[k];
        #pragma unroll 8
        for (int k = 0; k < 128; k++) gold += redG[k];
        float logz = LN2f * (Cshare[0] + Cshare[1] + __log2f(Z));
        float score = gold + trans_sh[stag[0]] + trans_sh[stag[LL - 1] * 64 + 1];
        atomicAdd(out, logz - score);   // out = -sum(scores - log_z)
    }
}

// ---------------- launch ----------------
extern "C" void kernel_launch(void* const* d_in, const int* in_sizes, int n_in,
                              void* d_out, int out_size) {
    const int*   x     = (const int*)d_in[0];
    const int*   tags  = (const int*)d_in[1];
    // d_in[2] = mask (ignored by reference CRF)
    const float* embed = (const float*)d_in[3];
    const float* W     = (const float*)d_in[4];
    const float* bias  = (const float*)d_in[5];
    const float* trans = (const float*)d_in[6];
    float* out = (float*)d_out;

    static bool attr_set = false;
    if (!attr_set) {
        cudaFuncSetAttribute(emis_kernel, cudaFuncAttributeMaxDynamicSharedMemorySize, SMEM_A_BYTES);
        attr_set = true;
    }

    emis_kernel<<<(VV + 127) / 128, 256, SMEM_A_BYTES>>>(embed, W, bias, out);
    crf_kernel<<<BB, 128>>>(x, tags, trans, out);
}